// round 16
// baseline (speedup 1.0000x reference)
#include <cuda_runtime.h>
#include <cuda_fp16.h>
#include <cstdint>

#define Bn 16
#define Hn 512
#define Wn 512
#define Rr 8
#define SEG1 16
#define SEGD 8
static constexpr size_t FSZ = (size_t)Bn * Hn * Wn;

// packed intermediate: per channel c, (17-col sum of a_c, 17-col sum of b_c)
__device__ __half2 g_bufH[3 * FSZ];

#define SIDX(p)  ((p) + ((p) >> 5))
#define SIDX4(p) ((p) + ((p) >> 3))

__device__ __forceinline__ float4 f4add(float4 a, float4 b) {
    return make_float4(a.x + b.x, a.y + b.y, a.z + b.z, a.w + b.w);
}
__device__ __forceinline__ float4 f4sub(float4 a, float4 b) {
    return make_float4(a.x - b.x, a.y - b.y, a.z - b.z, a.w - b.w);
}
__device__ __forceinline__ float frcp_fast(float v) {
    float r;
    asm("rcp.approx.f32 %0, %1;" : "=f"(r) : "f"(v));
    return r;
}
__device__ __forceinline__ void cpasync16(uint32_t saddr, const float* g) {
    asm volatile("cp.async.cg.shared.global [%0], [%1], 16;" :: "r"(saddr), "l"(g));
}
#define CP_COMMIT() asm volatile("cp.async.commit_group;" ::: "memory")
#define CP_WAIT0()  asm volatile("cp.async.wait_group 0;" ::: "memory")

// lo = {gr, gg, gb, gr*gy}; mid = {gg*gy, gb*gy, gr*gr, gg*gg}; hi = gb*gb
template <bool SUB>
__device__ __forceinline__ void accumMath(float4 x0, float4 x1, float4 x2,
                                          float4 vLo[4], float4 vMid[4], float vHi[4]) {
    float R[4] = {x0.x, x0.y, x0.z, x0.w};
    float G[4] = {x1.x, x1.y, x1.z, x1.w};
    float Bv[4] = {x2.x, x2.y, x2.z, x2.w};
#pragma unroll
    for (int c = 0; c < 4; ++c) {
        float gr = __saturatef(fmaf(R[c], 0.229f, 0.485f));
        float gg = __saturatef(fmaf(G[c], 0.224f, 0.456f));
        float gb = __saturatef(fmaf(Bv[c], 0.225f, 0.406f));
        float gy = (gr + gg + gb) * (1.0f / 3.0f);
        float4 dlo  = make_float4(gr, gg, gb, gr * gy);
        float4 dmid = make_float4(gg * gy, gb * gy, gr * gr, gg * gg);
        float  dhi  = gb * gb;
        if (SUB) {
            vLo[c] = f4sub(vLo[c], dlo);
            vMid[c] = f4sub(vMid[c], dmid);
            vHi[c] -= dhi;
        } else {
            vLo[c] = f4add(vLo[c], dlo);
            vMid[c] = f4add(vMid[c], dmid);
            vHi[c] += dhi;
        }
    }
}

template <bool SUB>
__device__ __forceinline__ void accumV(const float* __restrict__ xb, int h, int w0,
                                       float4 vLo[4], float4 vMid[4], float vHi[4]) {
    const size_t ch = (size_t)Hn * Wn;
    size_t o = (size_t)h * Wn + w0;
    float4 x0 = __ldg((const float4*)(xb + o));
    float4 x1 = __ldg((const float4*)(xb + o + ch));
    float4 x2 = __ldg((const float4*)(xb + o + 2 * ch));
    accumMath<SUB>(x0, x1, x2, vLo, vMid, vHi);
}

// ---------------- Fused kernel (cp.async smem prefetch of the add-row) ----------------
__global__ void __launch_bounds__(128) kF(const float* __restrict__ x) {
    __shared__ float4  sLo[600], sMid[600];
    __shared__ float   sHi[544];
    __shared__ float4  qLo[152], qMid[152];
    __shared__ float   qHi[136];
    __shared__ __half2 abS[3][544];
    __shared__ __half2 qab[3][136];
    __shared__ float4  stage[2][3][128];   // double-buffered add-row staging

    const int tid = threadIdx.x;
    const int h0  = blockIdx.x * SEG1;
    const int b   = blockIdx.y;
    const int w0  = tid * 4;
    const size_t ch = (size_t)Hn * Wn;
    const float* xb = x + (size_t)b * 3 * Hn * Wn;

    const float4 Z4 = make_float4(0.f, 0.f, 0.f, 0.f);
    const __half2 ZH = __floats2half2_rn(0.f, 0.f);

    if (tid < 8) {
        int cl = tid, cr = 520 + tid;
        sLo[SIDX4(cl)] = Z4;  sLo[SIDX4(cr)] = Z4;
        sMid[SIDX4(cl)] = Z4; sMid[SIDX4(cr)] = Z4;
        sHi[SIDX(cl)] = 0.f;  sHi[SIDX(cr)] = 0.f;
#pragma unroll
        for (int c = 0; c < 3; ++c) { abS[c][SIDX(cl)] = ZH; abS[c][SIDX(cr)] = ZH; }
    }
    if (tid < 2) {
        int tl = tid, tr = 130 + tid;
        qLo[SIDX4(tl)] = Z4;  qLo[SIDX4(tr)] = Z4;
        qMid[SIDX4(tl)] = Z4; qMid[SIDX4(tr)] = Z4;
        qHi[SIDX(tl)] = 0.f;  qHi[SIDX(tr)] = 0.f;
#pragma unroll
        for (int c = 0; c < 3; ++c) { qab[c][SIDX(tl)] = ZH; qab[c][SIDX(tr)] = ZH; }
    }

    float4 vLo[4], vMid[4];
    float  vHi[4];
#pragma unroll
    for (int c = 0; c < 4; ++c) { vLo[c] = Z4; vMid[c] = Z4; vHi[c] = 0.f; }

    // preload window rows [h0-8, h0+7]
    for (int h = h0 - Rr; h < h0 + Rr; ++h)
        if (h >= 0) accumV<false>(xb, h, w0, vLo, vMid, vHi);

    // prologue: async-issue the first add-row (h0+Rr, always < Hn since h0 <= 496)
    int p = 0;
    {
        size_t o = (size_t)(h0 + Rr) * Wn + w0;
        cpasync16((uint32_t)__cvta_generic_to_shared(&stage[0][0][tid]), xb + o);
        cpasync16((uint32_t)__cvta_generic_to_shared(&stage[0][1][tid]), xb + o + ch);
        cpasync16((uint32_t)__cvta_generic_to_shared(&stage[0][2][tid]), xb + o + 2 * ch);
    }
    CP_COMMIT();
    __syncthreads();

    const float AREA  = 289.0f;
    const float INVA  = 1.0f / 289.0f;
    const float EPSA2 = 289.0f * 289.0f * 0.001f;

#pragma unroll 1
    for (int h = h0; h < h0 + SEG1; ++h) {
        if (h + Rr < Hn) {
            CP_WAIT0();
            accumMath<false>(stage[p][0][tid], stage[p][1][tid], stage[p][2][tid],
                             vLo, vMid, vHi);
        }

        // W1: publish vertical sums + quads
        float4 qlo  = f4add(f4add(vLo[0], vLo[1]), f4add(vLo[2], vLo[3]));
        float4 qmid = f4add(f4add(vMid[0], vMid[1]), f4add(vMid[2], vMid[3]));
        float  qhio = (vHi[0] + vHi[1]) + (vHi[2] + vHi[3]);
#pragma unroll
        for (int c = 0; c < 4; ++c) {
            int cc = w0 + 8 + c;
            sLo[SIDX4(cc)] = vLo[c];
            sMid[SIDX4(cc)] = vMid[c];
            sHi[SIDX(cc)] = vHi[c];
        }
        qLo[SIDX4(tid + 2)] = qlo;
        qMid[SIDX4(tid + 2)] = qmid;
        qHi[SIDX(tid + 2)] = qhio;

        // async-issue next add-row into the other buffer (no registers held)
        if (h + 1 + Rr < Hn) {
            size_t o = (size_t)(h + 1 + Rr) * Wn + w0;
            cpasync16((uint32_t)__cvta_generic_to_shared(&stage[p ^ 1][0][tid]), xb + o);
            cpasync16((uint32_t)__cvta_generic_to_shared(&stage[p ^ 1][1][tid]), xb + o + ch);
            cpasync16((uint32_t)__cvta_generic_to_shared(&stage[p ^ 1][2][tid]), xb + o + 2 * ch);
        }
        CP_COMMIT();
        __syncthreads();   // S1 (also fences prev-row R2 reads of abS/qab)

        // R1: window assembly + a/b
        float4 WL = f4add(f4add(qLo[SIDX4(tid)], qLo[SIDX4(tid + 1)]),
                          f4add(qlo, qLo[SIDX4(tid + 3)]));
        WL = f4add(WL, sLo[SIDX4(w0 + 16)]);
        float4 WM = f4add(f4add(qMid[SIDX4(tid)], qMid[SIDX4(tid + 1)]),
                          f4add(qmid, qMid[SIDX4(tid + 3)]));
        WM = f4add(WM, sMid[SIDX4(w0 + 16)]);
        float WH = ((qHi[SIDX(tid)] + qHi[SIDX(tid + 1)]) + (qhio + qHi[SIDX(tid + 3)]))
                 + sHi[SIDX(w0 + 16)];

        float qa[3] = {0.f, 0.f, 0.f}, qb[3] = {0.f, 0.f, 0.f};
#pragma unroll
        for (int q = 0; q < 4; ++q) {
            float Si = (WL.x + WL.y + WL.z) * (1.0f / 3.0f);
            float Sg0 = WL.x, Sg1 = WL.y, Sg2 = WL.z;
            float n0 = fmaf(AREA, WL.w, -Sg0 * Si);
            float n1 = fmaf(AREA, WM.x, -Sg1 * Si);
            float n2 = fmaf(AREA, WM.y, -Sg2 * Si);
            float d0 = fmaf(AREA, WM.z, -Sg0 * Sg0) + EPSA2;
            float d1 = fmaf(AREA, WM.w, -Sg1 * Sg1) + EPSA2;
            float d2 = fmaf(AREA, WH,   -Sg2 * Sg2) + EPSA2;
            float p01 = d0 * d1, p12 = d1 * d2, p02 = d0 * d2;
            float r = frcp_fast(p01 * d2);
            float a0 = n0 * p12 * r;
            float a1 = n1 * p02 * r;
            float a2 = n2 * p01 * r;
            float b0 = (Si - a0 * Sg0) * INVA;
            float b1 = (Si - a1 * Sg1) * INVA;
            float b2 = (Si - a2 * Sg2) * INVA;
            int cc = w0 + 8 + q;
            abS[0][SIDX(cc)] = __floats2half2_rn(a0, b0);
            abS[1][SIDX(cc)] = __floats2half2_rn(a1, b1);
            abS[2][SIDX(cc)] = __floats2half2_rn(a2, b2);
            qa[0] += a0; qb[0] += b0;
            qa[1] += a1; qb[1] += b1;
            qa[2] += a2; qb[2] += b2;
            if (q < 3) {
                WL = f4sub(f4add(WL, sLo[SIDX4(w0 + q + 17)]), sLo[SIDX4(w0 + q)]);
                WM = f4sub(f4add(WM, sMid[SIDX4(w0 + q + 17)]), sMid[SIDX4(w0 + q)]);
                WH += sHi[SIDX(w0 + q + 17)] - sHi[SIDX(w0 + q)];
            }
        }
        __half2 qabOwn[3];
#pragma unroll
        for (int c = 0; c < 3; ++c) {
            qabOwn[c] = __floats2half2_rn(qa[c], qb[c]);
            qab[c][SIDX(tid + 2)] = qabOwn[c];
        }
        __syncthreads();   // S2

        // R2: horizontal sums of (a,b) in half2
        __align__(16) __half2 pack[3][4];
#pragma unroll
        for (int c = 0; c < 3; ++c) {
            __half2 T = __hadd2(__hadd2(qab[c][SIDX(tid)], qab[c][SIDX(tid + 1)]),
                                __hadd2(qabOwn[c], qab[c][SIDX(tid + 3)]));
            T = __hadd2(T, abS[c][SIDX(w0 + 16)]);
            pack[c][0] = T;
#pragma unroll
            for (int q = 1; q < 4; ++q) {
                T = __hsub2(__hadd2(T, abS[c][SIDX(w0 + 16 + q)]), abS[c][SIDX(w0 + q - 1)]);
                pack[c][q] = T;
            }
        }
        size_t row = ((size_t)b * Hn + h) * Wn + w0;
#pragma unroll
        for (int c = 0; c < 3; ++c)
            *(uint4*)(&g_bufH[(size_t)c * FSZ + row]) = *(const uint4*)(&pack[c][0]);

        int hl = h - Rr;
        if (hl >= 0) accumV<true>(xb, hl, w0, vLo, vMid, vHi);
        p ^= 1;
    }
}

// ---------------- Kernel D (vectorized, 4 cols/thread, SEGD=8) ----------------
__device__ __forceinline__ void addBufRow(size_t o, float sa[3][4], float sb[3][4], float sgn) {
#pragma unroll
    for (int c = 0; c < 3; ++c) {
        uint4 raw = __ldg((const uint4*)(&g_bufH[(size_t)c * FSZ + o]));
        __half2 p[4];
        p[0] = *(__half2*)&raw.x; p[1] = *(__half2*)&raw.y;
        p[2] = *(__half2*)&raw.z; p[3] = *(__half2*)&raw.w;
#pragma unroll
        for (int k = 0; k < 4; ++k) {
            float2 v = __half22float2(p[k]);
            sa[c][k] = fmaf(sgn, v.x, sa[c][k]);
            sb[c][k] = fmaf(sgn, v.y, sb[c][k]);
        }
    }
}

__global__ void __launch_bounds__(128) kD(const float* __restrict__ x, float* __restrict__ out) {
    const int w0 = threadIdx.x * 4;
    const int b  = blockIdx.z;
    const int h0 = blockIdx.y * SEGD;
    const size_t ch = (size_t)Hn * Wn;
    const size_t base = (size_t)b * Hn * Wn + w0;

    float sa[3][4], sb[3][4];
#pragma unroll
    for (int c = 0; c < 3; ++c)
#pragma unroll
        for (int k = 0; k < 4; ++k) { sa[c][k] = 0.f; sb[c][k] = 0.f; }

    for (int h = h0 - Rr; h < h0 + Rr; ++h)
        if (h >= 0) addBufRow(base + (size_t)h * Wn, sa, sb, 1.0f);

    const float* xb = x + (size_t)b * 3 * ch + w0;
    float* ob = out + (size_t)b * 3 * ch + w0;
    const float INVA = 1.0f / 289.0f;

    for (int h = h0; h < h0 + SEGD; ++h) {
        int he = h + Rr;
        size_t o = (size_t)h * Wn;
        float4 x0 = __ldg((const float4*)(xb + o));
        float4 x1 = __ldg((const float4*)(xb + o + ch));
        float4 x2 = __ldg((const float4*)(xb + o + 2 * ch));
        if (he < Hn) addBufRow(base + (size_t)he * Wn, sa, sb, 1.0f);

        float R[4] = {x0.x, x0.y, x0.z, x0.w};
        float G[4] = {x1.x, x1.y, x1.z, x1.w};
        float Bv[4] = {x2.x, x2.y, x2.z, x2.w};
        float o0[4], o1[4], o2[4];
#pragma unroll
        for (int k = 0; k < 4; ++k) {
            float gr = __saturatef(fmaf(R[k], 0.229f, 0.485f));
            float gg = __saturatef(fmaf(G[k], 0.224f, 0.456f));
            float gb = __saturatef(fmaf(Bv[k], 0.225f, 0.406f));
            o0[k] = gr - fmaf(sa[0][k], gr, sb[0][k]) * INVA;
            o1[k] = gg - fmaf(sa[1][k], gg, sb[1][k]) * INVA;
            o2[k] = gb - fmaf(sa[2][k], gb, sb[2][k]) * INVA;
        }
        *(float4*)(ob + o)          = make_float4(o0[0], o0[1], o0[2], o0[3]);
        *(float4*)(ob + o + ch)     = make_float4(o1[0], o1[1], o1[2], o1[3]);
        *(float4*)(ob + o + 2 * ch) = make_float4(o2[0], o2[1], o2[2], o2[3]);

        int hl = h - Rr;
        if (hl >= 0) addBufRow(base + (size_t)hl * Wn, sa, sb, -1.0f);
    }
}

extern "C" void kernel_launch(void* const* d_in, const int* in_sizes, int n_in,
                              void* d_out, int out_size) {
    const float* x = (const float*)d_in[0];
    float* out = (float*)d_out;
    (void)in_sizes; (void)n_in; (void)out_size;

    dim3 gF(Hn / SEG1, Bn);
    kF<<<gF, 128>>>(x);
    dim3 gD(1, Hn / SEGD, Bn);
    kD<<<gD, 128>>>(x, out);
}

// round 17
// speedup vs baseline: 1.0587x; 1.0587x over previous
#include <cuda_runtime.h>
#include <cuda_fp16.h>
#include <cstdint>

#define Bn 16
#define Hn 512
#define Wn 512
#define Rr 8
#define SEG1 16
#define SEGD 8
static constexpr size_t FSZ = (size_t)Bn * Hn * Wn;

// packed intermediate: per channel c, (17-col sum of a_c, 17-col sum of b_c)
__device__ __half2 g_bufH[3 * FSZ];

#define SIDX(p)  ((p) + ((p) >> 5))
#define SIDX4(p) ((p) + ((p) >> 3))

__device__ __forceinline__ float4 f4add(float4 a, float4 b) {
    return make_float4(a.x + b.x, a.y + b.y, a.z + b.z, a.w + b.w);
}
__device__ __forceinline__ float4 f4sub(float4 a, float4 b) {
    return make_float4(a.x - b.x, a.y - b.y, a.z - b.z, a.w - b.w);
}
__device__ __forceinline__ float frcp_fast(float v) {
    float r;
    asm("rcp.approx.f32 %0, %1;" : "=f"(r) : "f"(v));
    return r;
}
// streaming (evict-first) 16B store — output is never re-read
__device__ __forceinline__ void stg_cs(float* p, float4 v) {
    asm volatile("st.global.cs.v4.f32 [%0], {%1, %2, %3, %4};"
                 :: "l"(p), "f"(v.x), "f"(v.y), "f"(v.z), "f"(v.w) : "memory");
}

// lo = {gr, gg, gb, gr*gy}; mid = {gg*gy, gb*gy, gr*gr, gg*gg}; hi = gb*gb
template <bool SUB>
__device__ __forceinline__ void accumV(const float* __restrict__ xb, int h, int w0,
                                       float4 vLo[4], float4 vMid[4], float vHi[4]) {
    const size_t ch = (size_t)Hn * Wn;
    size_t o = (size_t)h * Wn + w0;
    float4 x0 = __ldg((const float4*)(xb + o));
    float4 x1 = __ldg((const float4*)(xb + o + ch));
    float4 x2 = __ldg((const float4*)(xb + o + 2 * ch));
    float R[4] = {x0.x, x0.y, x0.z, x0.w};
    float G[4] = {x1.x, x1.y, x1.z, x1.w};
    float Bv[4] = {x2.x, x2.y, x2.z, x2.w};
#pragma unroll
    for (int c = 0; c < 4; ++c) {
        float gr = __saturatef(fmaf(R[c], 0.229f, 0.485f));
        float gg = __saturatef(fmaf(G[c], 0.224f, 0.456f));
        float gb = __saturatef(fmaf(Bv[c], 0.225f, 0.406f));
        float gy = (gr + gg + gb) * (1.0f / 3.0f);
        float4 dlo  = make_float4(gr, gg, gb, gr * gy);
        float4 dmid = make_float4(gg * gy, gb * gy, gr * gr, gg * gg);
        float  dhi  = gb * gb;
        if (SUB) {
            vLo[c] = f4sub(vLo[c], dlo);
            vMid[c] = f4sub(vMid[c], dmid);
            vHi[c] -= dhi;
        } else {
            vLo[c] = f4add(vLo[c], dlo);
            vMid[c] = f4add(vMid[c], dmid);
            vHi[c] += dhi;
        }
    }
}

// ---------------- Fused kernel (R14 configuration) ----------------
__global__ void __launch_bounds__(128) kF(const float* __restrict__ x) {
    __shared__ float4  sLo[600], sMid[600];
    __shared__ float   sHi[544];
    __shared__ float4  qLo[152], qMid[152];
    __shared__ float   qHi[136];
    __shared__ __half2 abS[3][544];
    __shared__ __half2 qab[3][136];

    const int tid = threadIdx.x;
    const int h0  = blockIdx.x * SEG1;
    const int b   = blockIdx.y;
    const int w0  = tid * 4;
    const float* xb = x + (size_t)b * 3 * Hn * Wn;

    const float4 Z4 = make_float4(0.f, 0.f, 0.f, 0.f);
    const __half2 ZH = __floats2half2_rn(0.f, 0.f);

    if (tid < 8) {
        int cl = tid, cr = 520 + tid;
        sLo[SIDX4(cl)] = Z4;  sLo[SIDX4(cr)] = Z4;
        sMid[SIDX4(cl)] = Z4; sMid[SIDX4(cr)] = Z4;
        sHi[SIDX(cl)] = 0.f;  sHi[SIDX(cr)] = 0.f;
#pragma unroll
        for (int c = 0; c < 3; ++c) { abS[c][SIDX(cl)] = ZH; abS[c][SIDX(cr)] = ZH; }
    }
    if (tid < 2) {
        int tl = tid, tr = 130 + tid;
        qLo[SIDX4(tl)] = Z4;  qLo[SIDX4(tr)] = Z4;
        qMid[SIDX4(tl)] = Z4; qMid[SIDX4(tr)] = Z4;
        qHi[SIDX(tl)] = 0.f;  qHi[SIDX(tr)] = 0.f;
#pragma unroll
        for (int c = 0; c < 3; ++c) { qab[c][SIDX(tl)] = ZH; qab[c][SIDX(tr)] = ZH; }
    }

    float4 vLo[4], vMid[4];
    float  vHi[4];
#pragma unroll
    for (int c = 0; c < 4; ++c) { vLo[c] = Z4; vMid[c] = Z4; vHi[c] = 0.f; }

    // preload window rows [h0-8, h0+7]
#pragma unroll 2
    for (int h = h0 - Rr; h < h0 + Rr; ++h)
        if (h >= 0) accumV<false>(xb, h, w0, vLo, vMid, vHi);
    __syncthreads();

    const float AREA  = 289.0f;
    const float INVA  = 1.0f / 289.0f;
    const float EPSA2 = 289.0f * 289.0f * 0.001f;

    for (int h = h0; h < h0 + SEG1; ++h) {
        int he = h + Rr;
        if (he < Hn) accumV<false>(xb, he, w0, vLo, vMid, vHi);

        // W1: publish vertical sums + quads
        float4 qlo  = f4add(f4add(vLo[0], vLo[1]), f4add(vLo[2], vLo[3]));
        float4 qmid = f4add(f4add(vMid[0], vMid[1]), f4add(vMid[2], vMid[3]));
        float  qhio = (vHi[0] + vHi[1]) + (vHi[2] + vHi[3]);
#pragma unroll
        for (int c = 0; c < 4; ++c) {
            int cc = w0 + 8 + c;
            sLo[SIDX4(cc)] = vLo[c];
            sMid[SIDX4(cc)] = vMid[c];
            sHi[SIDX(cc)] = vHi[c];
        }
        qLo[SIDX4(tid + 2)] = qlo;
        qMid[SIDX4(tid + 2)] = qmid;
        qHi[SIDX(tid + 2)] = qhio;
        __syncthreads();   // S1 (also fences prev-row R2 reads of abS/qab)

        // R1: window assembly + a/b
        float4 WL = f4add(f4add(qLo[SIDX4(tid)], qLo[SIDX4(tid + 1)]),
                          f4add(qlo, qLo[SIDX4(tid + 3)]));
        WL = f4add(WL, sLo[SIDX4(w0 + 16)]);
        float4 WM = f4add(f4add(qMid[SIDX4(tid)], qMid[SIDX4(tid + 1)]),
                          f4add(qmid, qMid[SIDX4(tid + 3)]));
        WM = f4add(WM, sMid[SIDX4(w0 + 16)]);
        float WH = ((qHi[SIDX(tid)] + qHi[SIDX(tid + 1)]) + (qhio + qHi[SIDX(tid + 3)]))
                 + sHi[SIDX(w0 + 16)];

        float qa[3] = {0.f, 0.f, 0.f}, qb[3] = {0.f, 0.f, 0.f};
#pragma unroll
        for (int q = 0; q < 4; ++q) {
            float Si = (WL.x + WL.y + WL.z) * (1.0f / 3.0f);
            float Sg0 = WL.x, Sg1 = WL.y, Sg2 = WL.z;
            float n0 = fmaf(AREA, WL.w, -Sg0 * Si);
            float n1 = fmaf(AREA, WM.x, -Sg1 * Si);
            float n2 = fmaf(AREA, WM.y, -Sg2 * Si);
            float d0 = fmaf(AREA, WM.z, -Sg0 * Sg0) + EPSA2;
            float d1 = fmaf(AREA, WM.w, -Sg1 * Sg1) + EPSA2;
            float d2 = fmaf(AREA, WH,   -Sg2 * Sg2) + EPSA2;
            float p01 = d0 * d1, p12 = d1 * d2, p02 = d0 * d2;
            float r = frcp_fast(p01 * d2);
            float a0 = n0 * p12 * r;
            float a1 = n1 * p02 * r;
            float a2 = n2 * p01 * r;
            float b0 = (Si - a0 * Sg0) * INVA;
            float b1 = (Si - a1 * Sg1) * INVA;
            float b2 = (Si - a2 * Sg2) * INVA;
            int cc = w0 + 8 + q;
            abS[0][SIDX(cc)] = __floats2half2_rn(a0, b0);
            abS[1][SIDX(cc)] = __floats2half2_rn(a1, b1);
            abS[2][SIDX(cc)] = __floats2half2_rn(a2, b2);
            qa[0] += a0; qb[0] += b0;
            qa[1] += a1; qb[1] += b1;
            qa[2] += a2; qb[2] += b2;
            if (q < 3) {
                WL = f4sub(f4add(WL, sLo[SIDX4(w0 + q + 17)]), sLo[SIDX4(w0 + q)]);
                WM = f4sub(f4add(WM, sMid[SIDX4(w0 + q + 17)]), sMid[SIDX4(w0 + q)]);
                WH += sHi[SIDX(w0 + q + 17)] - sHi[SIDX(w0 + q)];
            }
        }
        __half2 qabOwn[3];
#pragma unroll
        for (int c = 0; c < 3; ++c) {
            qabOwn[c] = __floats2half2_rn(qa[c], qb[c]);
            qab[c][SIDX(tid + 2)] = qabOwn[c];
        }
        __syncthreads();   // S2

        // R2: horizontal sums of (a,b) in half2
        __align__(16) __half2 pack[3][4];
#pragma unroll
        for (int c = 0; c < 3; ++c) {
            __half2 T = __hadd2(__hadd2(qab[c][SIDX(tid)], qab[c][SIDX(tid + 1)]),
                                __hadd2(qabOwn[c], qab[c][SIDX(tid + 3)]));
            T = __hadd2(T, abS[c][SIDX(w0 + 16)]);
            pack[c][0] = T;
#pragma unroll
            for (int q = 1; q < 4; ++q) {
                T = __hsub2(__hadd2(T, abS[c][SIDX(w0 + 16 + q)]), abS[c][SIDX(w0 + q - 1)]);
                pack[c][q] = T;
            }
        }
        size_t row = ((size_t)b * Hn + h) * Wn + w0;
#pragma unroll
        for (int c = 0; c < 3; ++c)
            *(uint4*)(&g_bufH[(size_t)c * FSZ + row]) = *(const uint4*)(&pack[c][0]);

        int hl = h - Rr;
        if (hl >= 0) accumV<true>(xb, hl, w0, vLo, vMid, vHi);
    }
}

// ---------------- Kernel D (vectorized, 4 cols/thread, streaming output) ----------------
__device__ __forceinline__ void addBufRow(size_t o, float sa[3][4], float sb[3][4], float sgn) {
#pragma unroll
    for (int c = 0; c < 3; ++c) {
        uint4 raw = __ldg((const uint4*)(&g_bufH[(size_t)c * FSZ + o]));
        __half2 p[4];
        p[0] = *(__half2*)&raw.x; p[1] = *(__half2*)&raw.y;
        p[2] = *(__half2*)&raw.z; p[3] = *(__half2*)&raw.w;
#pragma unroll
        for (int k = 0; k < 4; ++k) {
            float2 v = __half22float2(p[k]);
            sa[c][k] = fmaf(sgn, v.x, sa[c][k]);
            sb[c][k] = fmaf(sgn, v.y, sb[c][k]);
        }
    }
}

__global__ void __launch_bounds__(128) kD(const float* __restrict__ x, float* __restrict__ out) {
    const int w0 = threadIdx.x * 4;
    const int b  = blockIdx.z;
    const int h0 = blockIdx.y * SEGD;
    const size_t ch = (size_t)Hn * Wn;
    const size_t base = (size_t)b * Hn * Wn + w0;

    float sa[3][4], sb[3][4];
#pragma unroll
    for (int c = 0; c < 3; ++c)
#pragma unroll
        for (int k = 0; k < 4; ++k) { sa[c][k] = 0.f; sb[c][k] = 0.f; }

    for (int h = h0 - Rr; h < h0 + Rr; ++h)
        if (h >= 0) addBufRow(base + (size_t)h * Wn, sa, sb, 1.0f);

    const float* xb = x + (size_t)b * 3 * ch + w0;
    float* ob = out + (size_t)b * 3 * ch + w0;
    const float INVA = 1.0f / 289.0f;

    for (int h = h0; h < h0 + SEGD; ++h) {
        int he = h + Rr;
        size_t o = (size_t)h * Wn;
        float4 x0 = __ldg((const float4*)(xb + o));
        float4 x1 = __ldg((const float4*)(xb + o + ch));
        float4 x2 = __ldg((const float4*)(xb + o + 2 * ch));
        if (he < Hn) addBufRow(base + (size_t)he * Wn, sa, sb, 1.0f);

        float R[4] = {x0.x, x0.y, x0.z, x0.w};
        float G[4] = {x1.x, x1.y, x1.z, x1.w};
        float Bv[4] = {x2.x, x2.y, x2.z, x2.w};
        float o0[4], o1[4], o2[4];
#pragma unroll
        for (int k = 0; k < 4; ++k) {
            float gr = __saturatef(fmaf(R[k], 0.229f, 0.485f));
            float gg = __saturatef(fmaf(G[k], 0.224f, 0.456f));
            float gb = __saturatef(fmaf(Bv[k], 0.225f, 0.406f));
            o0[k] = gr - fmaf(sa[0][k], gr, sb[0][k]) * INVA;
            o1[k] = gg - fmaf(sa[1][k], gg, sb[1][k]) * INVA;
            o2[k] = gb - fmaf(sa[2][k], gb, sb[2][k]) * INVA;
        }
        stg_cs(ob + o,          make_float4(o0[0], o0[1], o0[2], o0[3]));
        stg_cs(ob + o + ch,     make_float4(o1[0], o1[1], o1[2], o1[3]));
        stg_cs(ob + o + 2 * ch, make_float4(o2[0], o2[1], o2[2], o2[3]));

        int hl = h - Rr;
        if (hl >= 0) addBufRow(base + (size_t)hl * Wn, sa, sb, -1.0f);
    }
}

extern "C" void kernel_launch(void* const* d_in, const int* in_sizes, int n_in,
                              void* d_out, int out_size) {
    const float* x = (const float*)d_in[0];
    float* out = (float*)d_out;
    (void)in_sizes; (void)n_in; (void)out_size;

    dim3 gF(Hn / SEG1, Bn);
    kF<<<gF, 128>>>(x);
    dim3 gD(1, Hn / SEGD, Bn);
    kD<<<gD, 128>>>(x, out);
}